// round 17
// baseline (speedup 1.0000x reference)
#include <cuda_runtime.h>
#include <cuda_bf16.h>
#include <cuda_fp16.h>

#define NB 4
#define NL 2048
#define ND 1024
#define NH 16
#define DH 64

// ---------------- mma.sync GEMM config (fp16 2-split, 512 thr, 2 CTA/SM) ---
#define BK    32
#define ASTR  40
#define TILE_B (128*ASTR*2)          // 10240 B per tile (fp16)
#define STAGE_B (3*TILE_B)           // 30720 B per stage (A0, A1, B)
#define GSMEM  (2*STAGE_B)           // 61440 B
#define APLANE ((size_t)NB*NL*ND)
#define WPLANE ((size_t)ND*ND)

// ---------------- fused fp16 attention config (QT=64, proven) --------------
#define QT    64
#define KCH   128
#define KST   72
#define VST   136
#define KTILE (KCH*KST*2)
#define VTILE (64*VST*2)
#define VOFF  KTILE
#define MSK_OFF (KTILE + VTILE)
#define ASTAGE  (MSK_OFF + QT*16)
#define QOFF    (2*ASTAGE)
#define QSPL    (QT*KST*2)
#define RED_B   (8*QT*64*4)
#define RSPOFF  RED_B
#define INVOFF  (RSPOFF + 8*QT*4)
#define ASMEM   (INVOFF + QT*4)

// ---- cp.async ----
__device__ __forceinline__ void cpasync16(unsigned dst, const void* src) {
    asm volatile("cp.async.cg.shared.global [%0], [%1], 16;" :: "r"(dst), "l"(src) : "memory");
}
__device__ __forceinline__ void cp_commit() { asm volatile("cp.async.commit_group;" ::: "memory"); }
__device__ __forceinline__ void cp_wait0()  { asm volatile("cp.async.wait_group 0;" ::: "memory"); }
__device__ __forceinline__ void cp_wait1()  { asm volatile("cp.async.wait_group 1;" ::: "memory"); }
__device__ __forceinline__ unsigned smem_u32(const void* p) {
    unsigned a;
    asm("{ .reg .u64 t; cvta.to.shared.u64 t, %1; cvt.u32.u64 %0, t; }" : "=r"(a) : "l"(p));
    return a;
}
// ---- tensor-core (baseline PTX) ----
__device__ __forceinline__ void ldsm4(unsigned& r0, unsigned& r1,
                                      unsigned& r2, unsigned& r3, unsigned addr) {
    asm volatile("ldmatrix.sync.aligned.m8n8.x4.shared.b16 {%0,%1,%2,%3}, [%4];"
                 : "=r"(r0), "=r"(r1), "=r"(r2), "=r"(r3) : "r"(addr));
}
__device__ __forceinline__ void mma16816h(float* d, const unsigned* a,
                                          unsigned b0, unsigned b1) {
    asm volatile(
        "mma.sync.aligned.m16n8k16.row.col.f32.f16.f16.f32 "
        "{%0,%1,%2,%3}, {%4,%5,%6,%7}, {%8,%9}, {%0,%1,%2,%3};"
        : "+f"(d[0]), "+f"(d[1]), "+f"(d[2]), "+f"(d[3])
        : "r"(a[0]), "r"(a[1]), "r"(a[2]), "r"(a[3]), "r"(b0), "r"(b1));
}
__device__ __forceinline__ unsigned pkhf2(float pe, float po) {
    unsigned d;
    asm("cvt.rn.f16x2.f32 %0, %1, %2;" : "=r"(d) : "f"(po), "f"(pe));
    return d;
}
// fp16 2-split: hi = f16x2(pe,po), lo = f16x2 of residuals
__device__ __forceinline__ void split2h(float pe, float po, unsigned& hi, unsigned& lo) {
    hi = pkhf2(pe, po);
    const __half2 h = *reinterpret_cast<const __half2*>(&hi);
    lo = pkhf2(pe - __half2float(__low2half(h)), po - __half2float(__high2half(h)));
}

// Scratch device globals
__device__ __half g_a0h[3 * APLANE];   // A hi planes (K/V/Q inputs; plane 0 reused for ctx)
__device__ __half g_a1h[3 * APLANE];   // A residual planes
__device__ __half g_w0h[4 * WPLANE];   // W^T fp16 planes (Wk, Wv, Wq, Wo)
__device__ __half g_kh[APLANE];
__device__ __half g_qh[APLANE];
__device__ __half g_vth[APLANE];       // V^T [bh][d][l] written directly by proj epilogue
__device__ unsigned g_mbits[(size_t)NB * NL * (NL / 32)];

// ---------------------------------------------------------------------------
// convA (batched y=3): fp32 [M,1024] -> fp16 hi/lo splits
// ---------------------------------------------------------------------------
__global__ void convA_kernel(const float* __restrict__ s0,
                             const float* __restrict__ s1,
                             const float* __restrict__ s2)
{
    const int z = blockIdx.y;
    const float* src = (z == 0) ? s0 : (z == 1) ? s1 : s2;
    const size_t i = ((size_t)blockIdx.x * 256 + threadIdx.x) * 4;
    const float4 v = *(const float4*)(src + i);
    unsigned h0, l0, h1, l1;
    split2h(v.x, v.y, h0, l0);
    split2h(v.z, v.w, h1, l1);
    __half* a0 = g_a0h + (size_t)z * APLANE;
    __half* a1 = g_a1h + (size_t)z * APLANE;
    *(unsigned*)(a0 + i)     = h0;
    *(unsigned*)(a0 + i + 2) = h1;
    *(unsigned*)(a1 + i)     = l0;
    *(unsigned*)(a1 + i + 2) = l1;
}

// ---------------------------------------------------------------------------
// convW (batched z=4): fp32 W[k][n] -> transposed single fp16 plane [n][k]
// ---------------------------------------------------------------------------
__global__ void convW_kernel(const float* __restrict__ W0,
                             const float* __restrict__ W1,
                             const float* __restrict__ W2,
                             const float* __restrict__ W3)
{
    const int z = blockIdx.z;
    const float* W = (z == 0) ? W0 : (z == 1) ? W1 : (z == 2) ? W2 : W3;
    __shared__ float tile[32][33];
    const int k0 = blockIdx.y * 32, n0 = blockIdx.x * 32;
    for (int r = threadIdx.y; r < 32; r += 8)
        tile[r][threadIdx.x] = W[(size_t)(k0 + r) * ND + n0 + threadIdx.x];
    __syncthreads();
    __half* w0 = g_w0h + (size_t)z * WPLANE;
    for (int r = threadIdx.y; r < 32; r += 8) {
        const float v = tile[threadIdx.x][r];
        w0[(size_t)(n0 + r) * ND + k0 + threadIdx.x] = __float2half(v);
    }
}

// ---------------------------------------------------------------------------
// mask2bits
// ---------------------------------------------------------------------------
__global__ void mask2bits_kernel(const int* __restrict__ mask)
{
    const int gw = (blockIdx.x * 256 + threadIdx.x) >> 5;
    const int lane = threadIdx.x & 31;
    const int nwords = NB * NL * (NL / 32);
    const int step = (gridDim.x * 256) >> 5;
    for (int wv = gw; wv < nwords; wv += step) {
        const int v = mask[(size_t)wv * 32 + lane];
        const unsigned bits = __ballot_sync(0xffffffffu, v != 0);
        if (lane == 0) g_mbits[wv] = bits;
    }
}

// ---------------------------------------------------------------------------
// Shared GEMM mainloop (fp16 2-split), register-lean for 2 CTAs/SM.
// ---------------------------------------------------------------------------
#define GEMM_MAINLOOP(Aptr0, Aptr1, Wptr0)                                        \
    const __half* srcs[3] = { Aptr0, Aptr1, Wptr0 };                              \
    float acc[2][4][4];                                                           \
    _Pragma("unroll")                                                             \
    for (int mt = 0; mt < 2; mt++)                                                \
        _Pragma("unroll")                                                         \
        for (int nt = 0; nt < 4; nt++)                                            \
            _Pragma("unroll")                                                     \
            for (int r = 0; r < 4; r++) acc[mt][nt][r] = 0.f;                     \
    const int arow = (lane & 7) | (lane & 8);                                     \
    const int acol = (lane & 16) >> 1;                                            \
    const int brow = (lane & 7) | ((lane & 16) >> 1);                             \
    const int bcol = lane & 8;                                                    \
    {                                                                             \
        const unsigned sb = sb0;                                                  \
        const int row = t >> 2, seg = t & 3;                                      \
        _Pragma("unroll")                                                         \
        for (int s = 0; s < 3; s++)                                               \
            cpasync16(sb + s * TILE_B + (row * ASTR + seg * 8) * 2,               \
                      srcs[s] + (size_t)row * ND + seg * 8);                      \
        cp_commit();                                                              \
    }                                                                             \
    for (int c = 0; c < ND / BK; c++) {                                           \
        if (c + 1 < ND / BK) {                                                    \
            const unsigned sb = sb0 + ((c + 1) & 1) * STAGE_B;                    \
            const int k0 = (c + 1) * BK;                                          \
            const int row = t >> 2, seg = t & 3;                                  \
            _Pragma("unroll")                                                     \
            for (int s = 0; s < 3; s++)                                           \
                cpasync16(sb + s * TILE_B + (row * ASTR + seg * 8) * 2,           \
                          srcs[s] + (size_t)row * ND + k0 + seg * 8);             \
            cp_commit(); cp_wait1();                                              \
        } else { cp_wait0(); }                                                    \
        __syncthreads();                                                          \
        const unsigned sb = sb0 + (c & 1) * STAGE_B;                              \
        _Pragma("unroll")                                                         \
        for (int ks = 0; ks < 2; ks++) {                                          \
            const int kc = ks * 16;                                               \
            unsigned bf[2][4];                                                    \
            _Pragma("unroll")                                                     \
            for (int np = 0; np < 2; np++)                                        \
                ldsm4(bf[np][0], bf[np][1], bf[np][2], bf[np][3],                 \
                      sb + 2 * TILE_B +                                           \
                      (unsigned)(((wn + np * 16 + brow) * ASTR + kc + bcol) * 2)); \
            _Pragma("unroll")                                                     \
            for (int sp = 0; sp < 2; sp++) {                                      \
                unsigned af[2][4];                                                \
                _Pragma("unroll")                                                 \
                for (int mt = 0; mt < 2; mt++)                                    \
                    ldsm4(af[mt][0], af[mt][1], af[mt][2], af[mt][3],             \
                          sb + sp * TILE_B +                                      \
                          (unsigned)(((wm + mt * 16 + arow) * ASTR + kc + acol) * 2)); \
                _Pragma("unroll")                                                 \
                for (int mt = 0; mt < 2; mt++)                                    \
                    _Pragma("unroll")                                             \
                    for (int nt = 0; nt < 4; nt++) {                              \
                        const int np = nt >> 1, half = (nt & 1) * 2;              \
                        mma16816h(acc[mt][nt], af[mt], bf[np][half], bf[np][half + 1]); \
                    }                                                             \
            }                                                                     \
        }                                                                         \
        __syncthreads();                                                          \
    }

// ---------------------------------------------------------------------------
// Batched projection GEMM (grid.z = 3, 512 threads, 2 CTA/SM).
// z=0 -> K [bh][l][d]; z=1 -> V written TRANSPOSED to g_vth [bh][d][l];
// z=2 -> Q [bh][l][d] (pre-scaled).
// ---------------------------------------------------------------------------
__global__ void __launch_bounds__(512, 2) gemm_proj_kernel(
    const float* __restrict__ b0p, const float* __restrict__ b1p,
    const float* __restrict__ b2p)
{
    extern __shared__ char smem[];
    const unsigned sb0 = smem_u32(smem);
    const int t = threadIdx.x, lane = t & 31, wid = t >> 5;
    const int wm = (wid & 3) * 32, wn = (wid >> 2) * 32;
    const int n0 = blockIdx.x * 128, m0 = blockIdx.y * 128;
    const int z = blockIdx.z;
    const float* bias = (z == 0) ? b0p : (z == 1) ? b1p : b2p;
    const float scale = (z == 2) ? 0.125f : 1.0f;

    GEMM_MAINLOOP(g_a0h + z * APLANE + (size_t)m0 * ND,
                  g_a1h + z * APLANE + (size_t)m0 * ND,
                  g_w0h + z * WPLANE + (size_t)n0 * ND)

#pragma unroll
    for (int mt = 0; mt < 2; mt++)
#pragma unroll
        for (int nt = 0; nt < 4; nt++) {
            const int cc = n0 + wn + nt * 8 + (lane & 3) * 2;
            const float b0 = bias[cc], b1 = bias[cc + 1];
            const float v0 = (acc[mt][nt][0] + b0) * scale;
            const float v1 = (acc[mt][nt][1] + b1) * scale;
            const float v2 = (acc[mt][nt][2] + b0) * scale;
            const float v3 = (acc[mt][nt][3] + b1) * scale;
            const int r0 = m0 + wm + mt * 16 + (lane >> 2);
            const int bb = r0 >> 11, h = cc >> 6, d = cc & 63;
            const int l0 = r0 & (NL - 1);
            if (z == 1) {
                // V: write transposed [bh][d][l]
                __half* vt = g_vth + ((size_t)(bb * NH + h) * DH) * NL;
                vt[(size_t)d * NL + l0]           = __float2half(v0);
                vt[(size_t)(d + 1) * NL + l0]     = __float2half(v1);
                vt[(size_t)d * NL + l0 + 8]       = __float2half(v2);
                vt[(size_t)(d + 1) * NL + l0 + 8] = __float2half(v3);
            } else {
                __half* dsth = (z == 0) ? g_kh : g_qh;
                size_t o = ((size_t)(bb * NH + h) * NL + l0) * DH + d;
                *(unsigned*)(dsth + o) = pkhf2(v0, v1);
                o = ((size_t)(bb * NH + h) * NL + l0 + 8) * DH + d;
                *(unsigned*)(dsth + o) = pkhf2(v2, v3);
            }
        }
}

// ---------------------------------------------------------------------------
// Output GEMM (512 threads, 2 CTA/SM): (ctx @ Wo + bo) -> fp32
// ---------------------------------------------------------------------------
__global__ void __launch_bounds__(512, 2) gemm_out_kernel(
    const float* __restrict__ bias, float* __restrict__ dstf)
{
    extern __shared__ char smem[];
    const unsigned sb0 = smem_u32(smem);
    const int t = threadIdx.x, lane = t & 31, wid = t >> 5;
    const int wm = (wid & 3) * 32, wn = (wid >> 2) * 32;
    const int n0 = blockIdx.x * 128, m0 = blockIdx.y * 128;

    GEMM_MAINLOOP(g_a0h + (size_t)m0 * ND, g_a1h + (size_t)m0 * ND,
                  g_w0h + 3 * WPLANE + (size_t)n0 * ND)

#pragma unroll
    for (int mt = 0; mt < 2; mt++)
#pragma unroll
        for (int nt = 0; nt < 4; nt++) {
            const int cc = n0 + wn + nt * 8 + (lane & 3) * 2;
            const float b0 = bias[cc], b1 = bias[cc + 1];
            const int r0 = m0 + wm + mt * 16 + (lane >> 2);
            dstf[(size_t)r0 * ND + cc]           = acc[mt][nt][0] + b0;
            dstf[(size_t)r0 * ND + cc + 1]       = acc[mt][nt][1] + b1;
            dstf[(size_t)(r0 + 8) * ND + cc]     = acc[mt][nt][2] + b0;
            dstf[(size_t)(r0 + 8) * ND + cc + 1] = acc[mt][nt][3] + b1;
        }
}

// ---------------------------------------------------------------------------
// Fused fp16 flash attention; h==0 CTAs also normalize their attn_out slice.
// ---------------------------------------------------------------------------
__global__ void __launch_bounds__(256, 1) attn_fused_kernel(
    float* __restrict__ attn_out)
{
    extern __shared__ char smem[];
    const unsigned sb = smem_u32(smem);
    const int t = threadIdx.x, lane = t & 31, w = t >> 5;
    const int q0 = blockIdx.x * QT;
    const int h = blockIdx.y, b = blockIdx.z;
    const int bh = b * NH + h;

    const __half* kph = g_kh + (size_t)bh * NL * DH;
    const __half* vph = g_vth + (size_t)bh * DH * NL;
    const __half* qph = g_qh + (size_t)bh * NL * DH;

    const int arow = (lane & 7) | (lane & 8);
    const int acol = (lane & 16) >> 1;
    const int brow = (lane & 7) | ((lane & 16) >> 1);
    const int bcol = lane & 8;

#pragma unroll
    for (int i = 0; i < 2; i++) {
        const int u = t + i * 256;
        const int r = u >> 3, seg = u & 7;
        cpasync16(sb + QOFF + r * (KST * 2) + seg * 16,
                  qph + (size_t)(q0 + r) * DH + seg * 8);
    }

    const unsigned* mb = g_mbits;

#define AISSUE(c) do {                                                           \
    const unsigned st_ = sb + ((c) & 1) * ASTAGE;                                \
    const int kt_ = (c) * KCH;                                                   \
    _Pragma("unroll")                                                            \
    for (int i = 0; i < 4; i++) {                                                \
        const int u = t + i * 256;                                               \
        const int r = u >> 3, seg = u & 7;                                       \
        cpasync16(st_ + r * (KST * 2) + seg * 16,                                \
                  kph + (size_t)(kt_ + r) * DH + seg * 8);                       \
    }                                                                            \
    _Pragma("unroll")                                                            \
    for (int i = 0; i < 4; i++) {                                                \
        const int u = t + i * 256;                                               \
        const int r = u >> 4, seg = u & 15;                                      \
        cpasync16(st_ + VOFF + r * (VST * 2) + seg * 16,                         \
                  vph + (size_t)r * NL + kt_ + seg * 8);                         \
    }                                                                            \
    if (t < QT)                                                                  \
        cpasync16(st_ + MSK_OFF + t * 16,                                        \
                  mb + ((size_t)b * NL + q0 + t) * (NL / 32) + (kt_ >> 5));      \
    cp_commit();                                                                 \
} while (0)

    float accv[4][8][4];
#pragma unroll
    for (int mt = 0; mt < 4; mt++)
#pragma unroll
        for (int nt = 0; nt < 8; nt++)
#pragma unroll
            for (int r = 0; r < 4; r++) accv[mt][nt][r] = 0.f;
    float rs[4][2];
#pragma unroll
    for (int mt = 0; mt < 4; mt++) { rs[mt][0] = 0.f; rs[mt][1] = 0.f; }

    AISSUE(0);
    for (int c = 0; c < NL / KCH; c++) {
        if (c + 1 < NL / KCH) { AISSUE(c + 1); cp_wait1(); }
        else                  { cp_wait0(); }
        __syncthreads();
        const unsigned st = sb + (c & 1) * ASTAGE;
        const int kt = c * KCH;

        float accs[4][2][4];
#pragma unroll
        for (int mt = 0; mt < 4; mt++)
#pragma unroll
            for (int nt = 0; nt < 2; nt++)
#pragma unroll
                for (int r = 0; r < 4; r++) accs[mt][nt][r] = 0.f;

#pragma unroll
        for (int ks = 0; ks < 4; ks++) {
            const int kc = ks * 16;
            unsigned bk[4];
            ldsm4(bk[0], bk[1], bk[2], bk[3],
                  st + (unsigned)((w * 16 + brow) * (KST * 2) + (kc + bcol) * 2));
#pragma unroll
            for (int mt = 0; mt < 4; mt++) {
                unsigned aq[4];
                ldsm4(aq[0], aq[1], aq[2], aq[3],
                      sb + QOFF +
                      (unsigned)((mt * 16 + arow) * (KST * 2) + (kc + acol) * 2));
                mma16816h(accs[mt][0], aq, bk[0], bk[1]);
                mma16816h(accs[mt][1], aq, bk[2], bk[3]);
            }
        }

        unsigned bv[4][4];
#pragma unroll
        for (int np = 0; np < 4; np++)
            ldsm4(bv[np][0], bv[np][1], bv[np][2], bv[np][3],
                  st + VOFF +
                  (unsigned)((np * 16 + brow) * (VST * 2) + (w * 16 + bcol) * 2));

#pragma unroll
        for (int mt = 0; mt < 4; mt++) {
            const int r = lane >> 2;
            const unsigned mw0 = *(const unsigned*)(smem + (c & 1) * ASTAGE + MSK_OFF +
                                                    (mt * 16 + r) * 16 + (w >> 1) * 4);
            const unsigned mw1 = *(const unsigned*)(smem + (c & 1) * ASTAGE + MSK_OFF +
                                                    (mt * 16 + r + 8) * 16 + (w >> 1) * 4);
            const int bbase = (w & 1) * 16;
            float p[2][4];
#pragma unroll
            for (int nt = 0; nt < 2; nt++) {
                const int xb = bbase + nt * 8 + 2 * (lane & 3);
                p[nt][0] = ((mw0 >> xb) & 1)       ? 0.f : __expf(accs[mt][nt][0]);
                p[nt][1] = ((mw0 >> (xb + 1)) & 1) ? 0.f : __expf(accs[mt][nt][1]);
                p[nt][2] = ((mw1 >> xb) & 1)       ? 0.f : __expf(accs[mt][nt][2]);
                p[nt][3] = ((mw1 >> (xb + 1)) & 1) ? 0.f : __expf(accs[mt][nt][3]);
            }
            rs[mt][0] += p[0][0] + p[0][1] + p[1][0] + p[1][1];
            rs[mt][1] += p[0][2] + p[0][3] + p[1][2] + p[1][3];
            if (h == 0) {
                const size_t base = ((size_t)b * NL + q0 + mt * 16 + r) * NL + kt + w * 16;
                const int cc = 2 * (lane & 3);
                *(float2*)(attn_out + base + cc)               = make_float2(p[0][0], p[0][1]);
                *(float2*)(attn_out + base + 8 + cc)           = make_float2(p[1][0], p[1][1]);
                *(float2*)(attn_out + base + (size_t)8 * NL + cc)     = make_float2(p[0][2], p[0][3]);
                *(float2*)(attn_out + base + (size_t)8 * NL + 8 + cc) = make_float2(p[1][2], p[1][3]);
            }
            unsigned ap[4];
            ap[0] = pkhf2(p[0][0], p[0][1]);
            ap[1] = pkhf2(p[0][2], p[0][3]);
            ap[2] = pkhf2(p[1][0], p[1][1]);
            ap[3] = pkhf2(p[1][2], p[1][3]);
#pragma unroll
            for (int nt = 0; nt < 8; nt++) {
                const int np = nt >> 1, hf = (nt & 1) * 2;
                mma16816h(accv[mt][nt], ap, bv[np][hf], bv[np][hf + 1]);
            }
        }
        __syncthreads();
    }
#undef AISSUE

#pragma unroll
    for (int mt = 0; mt < 4; mt++)
#pragma unroll
        for (int hf = 0; hf < 2; hf++) {
            float v = rs[mt][hf];
            v += __shfl_xor_sync(0xffffffffu, v, 1);
            v += __shfl_xor_sync(0xffffffffu, v, 2);
            if ((lane & 3) == 0)
                *(float*)(smem + RSPOFF + (w * QT + mt * 16 + hf * 8 + (lane >> 2)) * 4) = v;
        }

    float* red = (float*)smem;
#pragma unroll
    for (int mt = 0; mt < 4; mt++)
#pragma unroll
        for (int nt = 0; nt < 8; nt++) {
            const int r0 = mt * 16 + (lane >> 2);
            const int cc = nt * 8 + 2 * (lane & 3);
            *(float2*)&red[(w * QT + r0) * 64 + (cc ^ ((r0 & 3) << 3))] =
                make_float2(accv[mt][nt][0], accv[mt][nt][1]);
            const int r1 = r0 + 8;
            *(float2*)&red[(w * QT + r1) * 64 + (cc ^ ((r1 & 3) << 3))] =
                make_float2(accv[mt][nt][2], accv[mt][nt][3]);
        }
    __syncthreads();

    float* invs = (float*)(smem + INVOFF);
    if (t < QT) {
        float s = 0.f;
#pragma unroll
        for (int ww = 0; ww < 8; ww++)
            s += *(float*)(smem + RSPOFF + (ww * QT + t) * 4);
        invs[t] = 1.f / s;
    }
    __syncthreads();

    // ctx epilogue -> fp16 splits into plane 0 of g_a0h/g_a1h
    for (int idx = t; idx < QT * DH / 2; idx += 256) {
        const int q = idx >> 5, dp = idx & 31;
        const int d0 = dp * 2, sw = (q & 3) << 3;
        float s0 = 0.f, s1 = 0.f;
#pragma unroll
        for (int ww = 0; ww < 8; ww++) {
            const float* rr = &red[(ww * QT + q) * 64];
            s0 += rr[d0 ^ sw];
            s1 += rr[(d0 + 1) ^ sw];
        }
        const float inv = invs[q];
        s0 *= inv; s1 *= inv;
        unsigned hi, lo;
        split2h(s0, s1, hi, lo);
        const size_t off = ((size_t)(b * NL + q0 + q)) * ND + h * DH + d0;
        *(unsigned*)(g_a0h + off) = hi;
        *(unsigned*)(g_a1h + off) = lo;
    }

    // h==0: normalize own attn_out slice in-kernel (replaces norm_attn kernel).
    // __syncthreads above orders this CTA's earlier global stores.
    if (h == 0) {
        for (int idx = t; idx < QT * (NL / 4); idx += 256) {
            const int q = idx >> 9;            // NL/4 = 512 float4 per row
            const int cp = idx & 511;
            const float inv = invs[q];
            float4* p = (float4*)(attn_out + ((size_t)b * NL + q0 + q) * NL) + cp;
            float4 v = *p;
            v.x *= inv; v.y *= inv; v.z *= inv; v.w *= inv;
            *p = v;
        }
    }
}

// ---------------------------------------------------------------------------
extern "C" void kernel_launch(void* const* d_in, const int* in_sizes, int n_in,
                              void* d_out, int out_size)
{
    const float* key   = (const float*)d_in[0];
    const float* value = (const float*)d_in[1];
    const float* query = (const float*)d_in[2];
    const int*   mask  = (const int*)d_in[3];
    const float* Wk = (const float*)d_in[4];
    const float* bk = (const float*)d_in[5];
    const float* Wv = (const float*)d_in[6];
    const float* bv = (const float*)d_in[7];
    const float* Wq = (const float*)d_in[8];
    const float* bq = (const float*)d_in[9];
    const float* Wo = (const float*)d_in[10];
    const float* bo = (const float*)d_in[11];

    float* out      = (float*)d_out;
    float* attn_out = out + (size_t)NB * NL * ND;

    static int attr_set = 0;
    if (!attr_set) {
        cudaFuncSetAttribute(gemm_proj_kernel, cudaFuncAttributeMaxDynamicSharedMemorySize, GSMEM);
        cudaFuncSetAttribute(gemm_out_kernel, cudaFuncAttributeMaxDynamicSharedMemorySize, GSMEM);
        cudaFuncSetAttribute(attn_fused_kernel, cudaFuncAttributeMaxDynamicSharedMemorySize, ASMEM);
        attr_set = 1;
    }

    const int convA_blocks = (NB * NL * ND) / (4 * 256);       // 8192
    const dim3 gemm_grid(ND / 128, (NB * NL) / 128, 3);        // 8 x 64 x 3

    convA_kernel<<<dim3(convA_blocks, 3), 256>>>(key, value, query);
    convW_kernel<<<dim3(ND / 32, ND / 32, 4), dim3(32, 8)>>>(Wk, Wv, Wq, Wo);
    mask2bits_kernel<<<1024, 256>>>(mask);
    gemm_proj_kernel<<<gemm_grid, 512, GSMEM>>>(bk, bv, bq);

    const dim3 attn_grid(NL / QT, NH, NB);   // 32 x 16 x 4
    attn_fused_kernel<<<attn_grid, 256, ASMEM>>>(attn_out);

    gemm_out_kernel<<<dim3(ND / 128, (NB * NL) / 128), 512, GSMEM>>>(bo, out);
}